// round 1
// baseline (speedup 1.0000x reference)
#include <cuda_runtime.h>
#include <cuda_bf16.h>
#include <math.h>

// ---------------- problem constants ----------------
#define NL_LAYERS 3
#define N_HEADS   16
#define EMB       1024
#define HEAD_DIM  64
#define SEQ_T     1024
#define BATCH     4
#define ROWS      (BATCH * SEQ_T)      // 4096
#define VOCAB     32000
#define E3        (3 * EMB)            // 3072
#define FF_DIM    (4 * EMB)            // 4096
#define LN_EPS    1e-5f
#define ATT_SCALE 0.03125f             // 1/sqrt(EMB) = 1/32  (reference uses 1/sqrt(C)!)

// ---------------- scratch (device globals; no allocation allowed) ----------------
__device__ float g_x   [ROWS * EMB];        // residual stream
__device__ float g_h   [ROWS * EMB];        // layernorm output
__device__ float g_qkv [ROWS * E3];         // fused qkv activations
__device__ float g_att [ROWS * EMB];        // attention output (heads concat)
__device__ float g_ff  [ROWS * FF_DIM];     // ffn hidden
__device__ float g_wqkv[NL_LAYERS * EMB * E3];  // prepacked [E, 3E] per layer
__device__ float g_logits[(size_t)ROWS * VOCAB]; // fallback logits if d_out too small
__device__ float g_rowloss[ROWS];

// ---------------- prepack wq/wk/wv -> [l][e][3E] ----------------
__global__ void prepack_qkv(const float* __restrict__ wq,
                            const float* __restrict__ wk,
                            const float* __restrict__ wv) {
    int idx = blockIdx.x * blockDim.x + threadIdx.x;
    int total = NL_LAYERS * EMB * E3;
    if (idx >= total) return;
    int l = idx / (EMB * E3);
    int r = idx % (EMB * E3);
    int e = r / E3;
    int c = r % E3;
    float v;
    if (c < EMB) {
        int h = c >> 6, d = c & 63;
        v = wq[(((size_t)l * N_HEADS + h) * EMB + e) * HEAD_DIM + d];
    } else if (c < 2 * EMB) {
        int c2 = c - EMB; int h = c2 >> 6, d = c2 & 63;
        v = wk[(((size_t)l * N_HEADS + h) * EMB + e) * HEAD_DIM + d];
    } else {
        int c2 = c - 2 * EMB; int h = c2 >> 6, d = c2 & 63;
        v = wv[(((size_t)l * N_HEADS + h) * EMB + e) * HEAD_DIM + d];
    }
    g_wqkv[idx] = v;
}

// ---------------- embedding ----------------
__global__ void embed_kernel(const int* __restrict__ ids,
                             const float* __restrict__ tok_emb,
                             const float* __restrict__ pos_emb) {
    int idx = blockIdx.x * blockDim.x + threadIdx.x;
    if (idx >= ROWS * EMB) return;
    int row = idx >> 10;           // /EMB
    int e   = idx & 1023;
    int t   = row & (SEQ_T - 1);
    int tok = ids[row];
    g_x[idx] = tok_emb[(size_t)tok * EMB + e] + pos_emb[(size_t)t * EMB + e];
}

// ---------------- layernorm (one block per row, E=1024) ----------------
__global__ void ln_kernel(const float* __restrict__ in,
                          const float* __restrict__ gamma,
                          const float* __restrict__ beta,
                          float* __restrict__ out) {
    int row = blockIdx.x;
    int tid = threadIdx.x;                 // 256 threads
    const float* p = in + (size_t)row * EMB;
    float s = 0.f, s2 = 0.f;
    #pragma unroll
    for (int i = 0; i < 4; i++) {
        float v = p[tid + i * 256];
        s += v; s2 += v * v;
    }
    __shared__ float rs[256], rs2[256];
    rs[tid] = s; rs2[tid] = s2;
    __syncthreads();
    for (int st = 128; st > 0; st >>= 1) {
        if (tid < st) { rs[tid] += rs[tid + st]; rs2[tid] += rs2[tid + st]; }
        __syncthreads();
    }
    float mu  = rs[0]  * (1.0f / EMB);
    float var = rs2[0] * (1.0f / EMB) - mu * mu;
    float inv = rsqrtf(var + LN_EPS);
    float* o = out + (size_t)row * EMB;
    #pragma unroll
    for (int i = 0; i < 4; i++) {
        int e = tid + i * 256;
        o[e] = (p[e] - mu) * inv * gamma[e] + beta[e];
    }
}

// ---------------- SGEMM: C = A[MxK] @ B[KxN] (+bias)(+res)(relu) ----------------
#define BM 64
#define BN 64
#define BK 16
__global__ __launch_bounds__(256)
void sgemm_kernel(const float* __restrict__ A, const float* __restrict__ B,
                  const float* __restrict__ bias, const float* __restrict__ res,
                  float* __restrict__ C, int M, int N, int K, int relu) {
    __shared__ float As[BK][BM];
    __shared__ float Bs[BK][BN + 4];
    int tid = threadIdx.x;
    int brow = blockIdx.y * BM;
    int bcol = blockIdx.x * BN;
    int tx = tid & 15, ty = tid >> 4;
    float acc[4][4] = {};
    int lrA = tid >> 4, lcA = tid & 15;    // A: 64x16 tile
    int lrB = tid >> 6, lcB = tid & 63;    // B: 16x64 tile
    for (int k0 = 0; k0 < K; k0 += BK) {
        #pragma unroll
        for (int i = 0; i < 4; i++) {
            int r = lrA + i * 16;
            As[lcA][r] = A[(size_t)(brow + r) * K + k0 + lcA];
        }
        #pragma unroll
        for (int i = 0; i < 4; i++) {
            int r = lrB + i * 4;
            Bs[r][lcB] = B[(size_t)(k0 + r) * N + bcol + lcB];
        }
        __syncthreads();
        #pragma unroll
        for (int kk = 0; kk < BK; kk++) {
            float a[4], b[4];
            #pragma unroll
            for (int i = 0; i < 4; i++) a[i] = As[kk][ty * 4 + i];
            #pragma unroll
            for (int j = 0; j < 4; j++) b[j] = Bs[kk][tx * 4 + j];
            #pragma unroll
            for (int i = 0; i < 4; i++)
                #pragma unroll
                for (int j = 0; j < 4; j++)
                    acc[i][j] += a[i] * b[j];
        }
        __syncthreads();
    }
    #pragma unroll
    for (int i = 0; i < 4; i++) {
        int row = brow + ty * 4 + i;
        #pragma unroll
        for (int j = 0; j < 4; j++) {
            int col = bcol + tx * 4 + j;
            float v = acc[i][j];
            if (bias) v += bias[col];
            if (res)  v += res[(size_t)row * N + col];
            if (relu) v = fmaxf(v, 0.f);
            C[(size_t)row * N + col] = v;
        }
    }
}

// ---------------- attention: one block per (b,h,t), 128 threads ----------------
__global__ __launch_bounds__(128)
void attn_kernel(const float* __restrict__ qkv, float* __restrict__ out) {
    int bid = blockIdx.x;                  // b*H*T + h*T + t
    int t = bid & (SEQ_T - 1);
    int h = (bid >> 10) & (N_HEADS - 1);
    int b = bid >> 14;
    int tid = threadIdx.x;

    __shared__ float qs[HEAD_DIM];
    __shared__ float sc[SEQ_T];
    __shared__ float red[128];

    int row_q = b * SEQ_T + t;
    const float* qp = qkv + (size_t)row_q * E3 + h * HEAD_DIM;
    if (tid < HEAD_DIM) qs[tid] = qp[tid];
    __syncthreads();

    // QK^T scores for s in [0, t]
    const float* kbase = qkv + (size_t)(b * SEQ_T) * E3 + EMB + h * HEAD_DIM;
    for (int s = tid; s <= t; s += 128) {
        const float4* kp4 = reinterpret_cast<const float4*>(kbase + (size_t)s * E3);
        float acc = 0.f;
        #pragma unroll
        for (int d4 = 0; d4 < 16; d4++) {
            float4 kk = kp4[d4];
            acc += qs[4*d4+0]*kk.x + qs[4*d4+1]*kk.y + qs[4*d4+2]*kk.z + qs[4*d4+3]*kk.w;
        }
        sc[s] = acc * ATT_SCALE;
    }
    __syncthreads();

    // max
    float m = -1e30f;
    for (int s = tid; s <= t; s += 128) m = fmaxf(m, sc[s]);
    red[tid] = m; __syncthreads();
    for (int st = 64; st > 0; st >>= 1) {
        if (tid < st) red[tid] = fmaxf(red[tid], red[tid + st]);
        __syncthreads();
    }
    m = red[0]; __syncthreads();

    // exp + sum
    float sum = 0.f;
    for (int s = tid; s <= t; s += 128) {
        float e = __expf(sc[s] - m);
        sc[s] = e; sum += e;
    }
    red[tid] = sum; __syncthreads();
    for (int st = 64; st > 0; st >>= 1) {
        if (tid < st) red[tid] += red[tid + st];
        __syncthreads();
    }
    float inv = 1.0f / red[0];
    __syncthreads();

    // O = softmax @ V  (threads 0..63 each own one d)
    if (tid < HEAD_DIM) {
        const float* vbase = qkv + (size_t)(b * SEQ_T) * E3 + 2 * EMB + h * HEAD_DIM + tid;
        float acc = 0.f;
        int s = 0;
        for (; s + 3 <= t; s += 4) {
            acc += sc[s]     * vbase[(size_t)s       * E3];
            acc += sc[s + 1] * vbase[(size_t)(s + 1) * E3];
            acc += sc[s + 2] * vbase[(size_t)(s + 2) * E3];
            acc += sc[s + 3] * vbase[(size_t)(s + 3) * E3];
        }
        for (; s <= t; s++) acc += sc[s] * vbase[(size_t)s * E3];
        out[(size_t)row_q * EMB + h * HEAD_DIM + tid] = acc * inv;
    }
}

// ---------------- loss ----------------
__global__ __launch_bounds__(256)
void loss_rows_kernel(const float* __restrict__ logits, const int* __restrict__ tgt) {
    int row = blockIdx.x;
    int tid = threadIdx.x;
    const float* lp = logits + (size_t)row * VOCAB;
    __shared__ float red[256];
    float m = -1e30f;
    for (int i = tid; i < VOCAB; i += 256) m = fmaxf(m, lp[i]);
    red[tid] = m; __syncthreads();
    for (int st = 128; st > 0; st >>= 1) {
        if (tid < st) red[tid] = fmaxf(red[tid], red[tid + st]);
        __syncthreads();
    }
    m = red[0]; __syncthreads();
    float s = 0.f;
    for (int i = tid; i < VOCAB; i += 256) s += __expf(lp[i] - m);
    red[tid] = s; __syncthreads();
    for (int st = 128; st > 0; st >>= 1) {
        if (tid < st) red[tid] += red[tid + st];
        __syncthreads();
    }
    if (tid == 0)
        g_rowloss[row] = -(lp[tgt[row]] - m - logf(red[0]));
}

__global__ __launch_bounds__(256)
void loss_final_kernel(float* __restrict__ out_loss) {
    int tid = threadIdx.x;
    __shared__ float red[256];
    float s = 0.f;
    #pragma unroll
    for (int i = 0; i < ROWS / 256; i++) s += g_rowloss[tid + i * 256];
    red[tid] = s; __syncthreads();
    for (int st = 128; st > 0; st >>= 1) {
        if (tid < st) red[tid] += red[tid + st];
        __syncthreads();
    }
    if (tid == 0) out_loss[0] = red[0] * (1.0f / ROWS);
}

// ---------------- launch ----------------
static void run_gemm(const float* A, const float* B, const float* bias,
                     const float* res, float* C, int M, int N, int K, int relu) {
    dim3 grid(N / BN, M / BM);
    sgemm_kernel<<<grid, 256>>>(A, B, bias, res, C, M, N, K, relu);
}

extern "C" void kernel_launch(void* const* d_in, const int* in_sizes, int n_in,
                              void* d_out, int out_size) {
    const int*   ids     = (const int*)  d_in[0];
    const int*   targets = (const int*)  d_in[1];
    const float* tok_emb = (const float*)d_in[2];
    const float* pos_emb = (const float*)d_in[3];
    const float* wq      = (const float*)d_in[4];
    const float* wk      = (const float*)d_in[5];
    const float* wv      = (const float*)d_in[6];
    const float* wo      = (const float*)d_in[7];
    const float* bo      = (const float*)d_in[8];
    const float* ln1_g   = (const float*)d_in[9];
    const float* ln1_b   = (const float*)d_in[10];
    const float* w1      = (const float*)d_in[11];
    const float* b1      = (const float*)d_in[12];
    const float* w2      = (const float*)d_in[13];
    const float* b2      = (const float*)d_in[14];
    const float* lnf_g   = (const float*)d_in[15];
    const float* lnf_b   = (const float*)d_in[16];
    const float* lm_w    = (const float*)d_in[17];
    const float* lm_b    = (const float*)d_in[18];

    float* x;   cudaGetSymbolAddress((void**)&x,   g_x);
    float* h;   cudaGetSymbolAddress((void**)&h,   g_h);
    float* qkv; cudaGetSymbolAddress((void**)&qkv, g_qkv);
    float* att; cudaGetSymbolAddress((void**)&att, g_att);
    float* ff;  cudaGetSymbolAddress((void**)&ff,  g_ff);
    float* wqkv;cudaGetSymbolAddress((void**)&wqkv,g_wqkv);
    float* glog;cudaGetSymbolAddress((void**)&glog,g_logits);

    const long long NLOG = (long long)ROWS * VOCAB;
    float* logits = ((long long)out_size >= NLOG) ? (float*)d_out : glog;

    // prepack fused qkv weights
    {
        int total = NL_LAYERS * EMB * E3;
        prepack_qkv<<<(total + 255) / 256, 256>>>(wq, wk, wv);
    }

    // embedding
    embed_kernel<<<(ROWS * EMB + 255) / 256, 256>>>(ids, tok_emb, pos_emb);

    for (int l = 0; l < NL_LAYERS; l++) {
        const float* g1 = ln1_g + l * EMB;
        const float* bt1 = ln1_b + l * EMB;
        // h = LN(x)
        ln_kernel<<<ROWS, 256>>>(x, g1, bt1, h);
        // qkv = h @ Wqkv
        run_gemm(h, wqkv + (size_t)l * EMB * E3, nullptr, nullptr, qkv,
                 ROWS, E3, EMB, 0);
        // attention
        attn_kernel<<<BATCH * N_HEADS * SEQ_T, 128>>>(qkv, att);
        // x = x + att @ wo + bo
        run_gemm(att, wo + (size_t)l * EMB * EMB, bo + l * EMB, x, x,
                 ROWS, EMB, EMB, 0);
        // h = LN(x)   (reference reuses ln1 before FFN)
        ln_kernel<<<ROWS, 256>>>(x, g1, bt1, h);
        // ff = relu(h @ w1 + b1)
        run_gemm(h, w1 + (size_t)l * EMB * FF_DIM, b1 + l * FF_DIM, nullptr, ff,
                 ROWS, FF_DIM, EMB, 1);
        // x = x + ff @ w2 + b2
        run_gemm(ff, w2 + (size_t)l * FF_DIM * EMB, b2 + l * EMB, x, x,
                 ROWS, EMB, FF_DIM, 0);
    }

    // final LN + lm head
    ln_kernel<<<ROWS, 256>>>(x, lnf_g, lnf_b, h);
    run_gemm(h, lm_w, lm_b, nullptr, logits, ROWS, VOCAB, EMB, 0);

    // loss (deterministic two-stage reduction)
    if (out_size == 1 || (long long)out_size > NLOG) {
        loss_rows_kernel<<<ROWS, 256>>>(logits, targets);
        float* loss_dst = (out_size == 1) ? (float*)d_out
                                          : ((float*)d_out + NLOG);
        loss_final_kernel<<<1, 256>>>(loss_dst);
    }
}

// round 3
// speedup vs baseline: 2.4043x; 2.4043x over previous
#include <cuda_runtime.h>
#include <cuda_bf16.h>
#include <math.h>
#include <stdint.h>

// ---------------- problem constants ----------------
#define NL_LAYERS 3
#define N_HEADS   16
#define EMB       1024
#define HEAD_DIM  64
#define SEQ_T     1024
#define BATCH     4
#define ROWS      (BATCH * SEQ_T)      // 4096
#define VOCAB     32000
#define E3        (3 * EMB)            // 3072
#define FF_DIM    (4 * EMB)            // 4096
#define LN_EPS    1e-5f
#define ATT_SCALE 0.03125f             // 1/sqrt(EMB) = 1/32  (reference uses 1/sqrt(C)!)

// ---------------- scratch (device globals; no allocation allowed) ----------------
__device__ float g_x   [ROWS * EMB];        // residual stream
__device__ float g_h   [ROWS * EMB];        // layernorm output
__device__ float g_qkv [ROWS * E3];         // fused qkv activations
__device__ float g_att [ROWS * EMB];        // attention output (heads concat)
__device__ float g_ff  [ROWS * FF_DIM];     // ffn hidden
__device__ float g_wqkv[NL_LAYERS * EMB * E3];  // prepacked [E, 3E] per layer
__device__ float g_logits[(size_t)ROWS * VOCAB]; // fallback logits if d_out too small
__device__ float g_rowloss[ROWS];

// ---------------- prepack wq/wk/wv -> [l][e][3E] ----------------
__global__ void prepack_qkv(const float* __restrict__ wq,
                            const float* __restrict__ wk,
                            const float* __restrict__ wv) {
    int idx = blockIdx.x * blockDim.x + threadIdx.x;
    int total = NL_LAYERS * EMB * E3;
    if (idx >= total) return;
    int l = idx / (EMB * E3);
    int r = idx % (EMB * E3);
    int e = r / E3;
    int c = r % E3;
    float v;
    if (c < EMB) {
        int h = c >> 6, d = c & 63;
        v = wq[(((size_t)l * N_HEADS + h) * EMB + e) * HEAD_DIM + d];
    } else if (c < 2 * EMB) {
        int c2 = c - EMB; int h = c2 >> 6, d = c2 & 63;
        v = wk[(((size_t)l * N_HEADS + h) * EMB + e) * HEAD_DIM + d];
    } else {
        int c2 = c - 2 * EMB; int h = c2 >> 6, d = c2 & 63;
        v = wv[(((size_t)l * N_HEADS + h) * EMB + e) * HEAD_DIM + d];
    }
    g_wqkv[idx] = v;
}

// ---------------- embedding ----------------
__global__ void embed_kernel(const int* __restrict__ ids,
                             const float* __restrict__ tok_emb,
                             const float* __restrict__ pos_emb) {
    int idx = blockIdx.x * blockDim.x + threadIdx.x;
    if (idx >= ROWS * EMB) return;
    int row = idx >> 10;           // /EMB
    int e   = idx & 1023;
    int t   = row & (SEQ_T - 1);
    int tok = ids[row];
    g_x[idx] = tok_emb[(size_t)tok * EMB + e] + pos_emb[(size_t)t * EMB + e];
}

// ---------------- layernorm (one block per row, E=1024) ----------------
__global__ void ln_kernel(const float* __restrict__ in,
                          const float* __restrict__ gamma,
                          const float* __restrict__ beta,
                          float* __restrict__ out) {
    int row = blockIdx.x;
    int tid = threadIdx.x;                 // 256 threads
    const float* p = in + (size_t)row * EMB;
    float s = 0.f, s2 = 0.f;
    #pragma unroll
    for (int i = 0; i < 4; i++) {
        float v = p[tid + i * 256];
        s += v; s2 += v * v;
    }
    __shared__ float rs[256], rs2[256];
    rs[tid] = s; rs2[tid] = s2;
    __syncthreads();
    for (int st = 128; st > 0; st >>= 1) {
        if (tid < st) { rs[tid] += rs[tid + st]; rs2[tid] += rs2[tid + st]; }
        __syncthreads();
    }
    float mu  = rs[0]  * (1.0f / EMB);
    float var = rs2[0] * (1.0f / EMB) - mu * mu;
    float inv = rsqrtf(var + LN_EPS);
    float* o = out + (size_t)row * EMB;
    #pragma unroll
    for (int i = 0; i < 4; i++) {
        int e = tid + i * 256;
        o[e] = (p[e] - mu) * inv * gamma[e] + beta[e];
    }
}

// ---------------- tf32 -> u32 convert ----------------
__device__ __forceinline__ unsigned int f2tf32(float f) {
    unsigned int u;
    asm("cvt.rna.tf32.f32 %0, %1;" : "=r"(u) : "f"(f));
    return u;
}

#define MMA_TF32(d, a, b)                                                     \
    asm volatile("mma.sync.aligned.m16n8k8.row.col.f32.tf32.tf32.f32 "        \
                 "{%0,%1,%2,%3}, {%4,%5,%6,%7}, {%8,%9}, {%0,%1,%2,%3};"      \
                 : "+f"(d[0]), "+f"(d[1]), "+f"(d[2]), "+f"(d[3])             \
                 : "r"(a[0]), "r"(a[1]), "r"(a[2]), "r"(a[3]),                \
                   "r"(b[0]), "r"(b[1]))

// ---------------- TF32 tensor-core GEMM ----------------
// C[MxN] = A[MxK] @ B[KxN] (+bias)(+res)(relu)
// CTA tile 128x128x32, 8 warps (2m x 4n), warp tile 64x32, mma m16n8k8.
// Shared layouts chosen for conflict-free fragment reads:
//   As[m][k], stride 36:  read bank = (4m+k)%32 == lane  -> 0 conflicts
//   Bs[k][n], stride 136: read bank = (8k+n)%32 distinct -> 0 conflicts
#define TBM 128
#define TBN 128
#define TBK 32
#define ASTRIDE 36
#define BSTRIDE 136

__global__ __launch_bounds__(256)
void tgemm_kernel(const float* __restrict__ A, const float* __restrict__ B,
                  const float* __restrict__ bias, const float* __restrict__ res,
                  float* __restrict__ C, int M, int N, int K, int relu) {
    __shared__ unsigned int As[TBM * ASTRIDE];
    __shared__ unsigned int Bs[TBK * BSTRIDE];

    const int tid  = threadIdx.x;
    const int lane = tid & 31;
    const int wid  = tid >> 5;
    const int wm   = (wid & 1) * 64;        // warp row offset in tile
    const int wn   = (wid >> 1) * 32;       // warp col offset in tile
    const int g    = lane >> 2;             // group id 0..7
    const int tg   = lane & 3;              // thread-in-group 0..3

    const int brow = blockIdx.y * TBM;
    const int bcol = blockIdx.x * TBN;

    const float* Ab = A + (size_t)brow * K;
    const float* Bb = B + bcol;

    // load index mapping (float4 granularity)
    const int arow = tid >> 3;              // 0..31 (+ i*32)
    const int acg  = (tid & 7) * 4;         // col 0..28
    const int brw  = tid >> 5;              // 0..7 (+ i*8)
    const int bcg  = (tid & 31) * 4;        // col 0..124

    float acc[4][4][4];
    #pragma unroll
    for (int i = 0; i < 4; i++)
        #pragma unroll
        for (int j = 0; j < 4; j++)
            #pragma unroll
            for (int c = 0; c < 4; c++) acc[i][j][c] = 0.f;

    float4 pa[4], pb[4];

    // prologue: load tile 0
    #pragma unroll
    for (int i = 0; i < 4; i++)
        pa[i] = *(const float4*)(Ab + (size_t)(arow + i * 32) * K + acg);
    #pragma unroll
    for (int i = 0; i < 4; i++)
        pb[i] = *(const float4*)(Bb + (size_t)(brw + i * 8) * N + bcg);

    const int KT = K / TBK;
    for (int kt = 0; kt < KT; kt++) {
        // store prefetched tile to shared (tf32-converted)
        #pragma unroll
        for (int i = 0; i < 4; i++) {
            unsigned int* p = &As[(arow + i * 32) * ASTRIDE + acg];
            p[0] = f2tf32(pa[i].x); p[1] = f2tf32(pa[i].y);
            p[2] = f2tf32(pa[i].z); p[3] = f2tf32(pa[i].w);
        }
        #pragma unroll
        for (int i = 0; i < 4; i++) {
            unsigned int* p = &Bs[(brw + i * 8) * BSTRIDE + bcg];
            p[0] = f2tf32(pb[i].x); p[1] = f2tf32(pb[i].y);
            p[2] = f2tf32(pb[i].z); p[3] = f2tf32(pb[i].w);
        }
        __syncthreads();

        // prefetch next tile
        if (kt + 1 < KT) {
            int k0 = (kt + 1) * TBK;
            #pragma unroll
            for (int i = 0; i < 4; i++)
                pa[i] = *(const float4*)(Ab + (size_t)(arow + i * 32) * K + k0 + acg);
            #pragma unroll
            for (int i = 0; i < 4; i++)
                pb[i] = *(const float4*)(Bb + (size_t)(k0 + brw + i * 8) * N + bcg);
        }

        // compute: 4 k-steps of 8
        #pragma unroll
        for (int ks = 0; ks < 4; ks++) {
            const int k = ks * 8 + tg;
            unsigned int af[4][4], bf[4][2];
            #pragma unroll
            for (int mt = 0; mt < 4; mt++) {
                int r = wm + mt * 16 + g;
                af[mt][0] = As[r * ASTRIDE + k];
                af[mt][1] = As[(r + 8) * ASTRIDE + k];
                af[mt][2] = As[r * ASTRIDE + k + 4];
                af[mt][3] = As[(r + 8) * ASTRIDE + k + 4];
            }
            #pragma unroll
            for (int nt = 0; nt < 4; nt++) {
                int c = wn + nt * 8 + g;
                bf[nt][0] = Bs[k * BSTRIDE + c];
                bf[nt][1] = Bs[(k + 4) * BSTRIDE + c];
            }
            #pragma unroll
            for (int mt = 0; mt < 4; mt++)
                #pragma unroll
                for (int nt = 0; nt < 4; nt++)
                    MMA_TF32(acc[mt][nt], af[mt], bf[nt]);
        }
        __syncthreads();
    }

    // epilogue
    #pragma unroll
    for (int mt = 0; mt < 4; mt++) {
        int r0 = brow + wm + mt * 16 + g;
        #pragma unroll
        for (int nt = 0; nt < 4; nt++) {
            int c0 = bcol + wn + nt * 8 + tg * 2;
            float b0 = 0.f, b1 = 0.f;
            if (bias) { b0 = bias[c0]; b1 = bias[c0 + 1]; }
            #pragma unroll
            for (int half = 0; half < 2; half++) {
                int r = r0 + half * 8;
                float v0 = acc[mt][nt][half * 2 + 0] + b0;
                float v1 = acc[mt][nt][half * 2 + 1] + b1;
                if (res) {
                    const float2 rr = *(const float2*)(res + (size_t)r * N + c0);
                    v0 += rr.x; v1 += rr.y;
                }
                if (relu) { v0 = fmaxf(v0, 0.f); v1 = fmaxf(v1, 0.f); }
                float2 o; o.x = v0; o.y = v1;
                *(float2*)(C + (size_t)r * N + c0) = o;
            }
        }
    }
}

// ---------------- attention: one block per (b,h,t), 128 threads ----------------
__global__ __launch_bounds__(128)
void attn_kernel(const float* __restrict__ qkv, float* __restrict__ out) {
    int bid = blockIdx.x;                  // b*H*T + h*T + t
    int t = bid & (SEQ_T - 1);
    int h = (bid >> 10) & (N_HEADS - 1);
    int b = bid >> 14;
    int tid = threadIdx.x;

    __shared__ float qs[HEAD_DIM];
    __shared__ float sc[SEQ_T];
    __shared__ float red[128];

    int row_q = b * SEQ_T + t;
    const float* qp = qkv + (size_t)row_q * E3 + h * HEAD_DIM;
    if (tid < HEAD_DIM) qs[tid] = qp[tid];
    __syncthreads();

    // QK^T scores for s in [0, t]
    const float* kbase = qkv + (size_t)(b * SEQ_T) * E3 + EMB + h * HEAD_DIM;
    for (int s = tid; s <= t; s += 128) {
        const float4* kp4 = reinterpret_cast<const float4*>(kbase + (size_t)s * E3);
        float acc = 0.f;
        #pragma unroll
        for (int d4 = 0; d4 < 16; d4++) {
            float4 kk = kp4[d4];
            acc += qs[4*d4+0]*kk.x + qs[4*d4+1]*kk.y + qs[4*d4+2]*kk.z + qs[4*d4+3]*kk.w;
        }
        sc[s] = acc * ATT_SCALE;
    }
    __syncthreads();

    // max
    float m = -1e30f;
    for (int s = tid; s <= t; s += 128) m = fmaxf(m, sc[s]);
    red[tid] = m; __syncthreads();
    for (int st = 64; st > 0; st >>= 1) {
        if (tid < st) red[tid] = fmaxf(red[tid], red[tid + st]);
        __syncthreads();
    }
    m = red[0]; __syncthreads();

    // exp + sum
    float sum = 0.f;
    for (int s = tid; s <= t; s += 128) {
        float e = __expf(sc[s] - m);
        sc[s] = e; sum += e;
    }
    red[tid] = sum; __syncthreads();
    for (int st = 64; st > 0; st >>= 1) {
        if (tid < st) red[tid] += red[tid + st];
        __syncthreads();
    }
    float inv = 1.0f / red[0];
    __syncthreads();

    // O = softmax @ V  (threads 0..63 each own one d)
    if (tid < HEAD_DIM) {
        const float* vbase = qkv + (size_t)(b * SEQ_T) * E3 + 2 * EMB + h * HEAD_DIM + tid;
        float acc = 0.f;
        int s = 0;
        for (; s + 3 <= t; s += 4) {
            acc += sc[s]     * vbase[(size_t)s       * E3];
            acc += sc[s + 1] * vbase[(size_t)(s + 1) * E3];
            acc += sc[s + 2] * vbase[(size_t)(s + 2) * E3];
            acc += sc[s + 3] * vbase[(size_t)(s + 3) * E3];
        }
        for (; s <= t; s++) acc += sc[s] * vbase[(size_t)s * E3];
        out[(size_t)row_q * EMB + h * HEAD_DIM + tid] = acc * inv;
    }
}

// ---------------- loss ----------------
__global__ __launch_bounds__(256)
void loss_rows_kernel(const float* __restrict__ logits, const int* __restrict__ tgt) {
    int row = blockIdx.x;
    int tid = threadIdx.x;
    const float* lp = logits + (size_t)row * VOCAB;
    __shared__ float red[256];
    float m = -1e30f;
    for (int i = tid; i < VOCAB; i += 256) m = fmaxf(m, lp[i]);
    red[tid] = m; __syncthreads();
    for (int st = 128; st > 0; st >>= 1) {
        if (tid < st) red[tid] = fmaxf(red[tid], red[tid + st]);
        __syncthreads();
    }
    m = red[0]; __syncthreads();
    float s = 0.f;
    for (int i = tid; i < VOCAB; i += 256) s += __expf(lp[i] - m);
    red[tid] = s; __syncthreads();
    for (int st = 128; st > 0; st >>= 1) {
        if (tid < st) red[tid] += red[tid + st];
        __syncthreads();
    }
    if (tid == 0)
        g_rowloss[row] = -(lp[tgt[row]] - m - logf(red[0]));
}

__global__ __launch_bounds__(256)
void loss_final_kernel(float* __restrict__ out_loss) {
    int tid = threadIdx.x;
    __shared__ float red[256];
    float s = 0.f;
    #pragma unroll
    for (int i = 0; i < ROWS / 256; i++) s += g_rowloss[tid + i * 256];
    red[tid] = s; __syncthreads();
    for (int st = 128; st > 0; st >>= 1) {
        if (tid < st) red[tid] += red[tid + st];
        __syncthreads();
    }
    if (tid == 0) out_loss[0] = red[0] * (1.0f / ROWS);
}

// ---------------- launch ----------------
static void run_gemm(const float* A, const float* B, const float* bias,
                     const float* res, float* C, int M, int N, int K, int relu) {
    dim3 grid(N / TBN, M / TBM);
    tgemm_kernel<<<grid, 256>>>(A, B, bias, res, C, M, N, K, relu);
}

extern "C" void kernel_launch(void* const* d_in, const int* in_sizes, int n_in,
                              void* d_out, int out_size) {
    const int*   ids     = (const int*)  d_in[0];
    const int*   targets = (const int*)  d_in[1];
    const float* tok_emb = (const float*)d_in[2];
    const float* pos_emb = (const float*)d_in[3];
    const float* wq      = (const float*)d_in[4];
    const float* wk      = (const float*)d_in[5];
    const float* wv      = (const float*)d_in[6];
    const float* wo      = (const float*)d_in[7];
    const float* bo      = (const float*)d_in[8];
    const float* ln1_g   = (const float*)d_in[9];
    const float* ln1_b   = (const float*)d_in[10];
    const float* w1      = (const float*)d_in[11];
    const float* b1      = (const float*)d_in[12];
    const float* w2      = (const float*)d_in[13];
    const float* b2      = (const float*)d_in[14];
    const float* lnf_g   = (const float*)d_in[15];
    const float* lnf_b   = (const float*)d_in[16];
    const float* lm_w    = (const float*)d_in[17];
    const float* lm_b    = (const float*)d_in[18];

    float* x;   cudaGetSymbolAddress((void**)&x,   g_x);
    float* h;   cudaGetSymbolAddress((void**)&h,   g_h);
    float* qkv; cudaGetSymbolAddress((void**)&qkv, g_qkv);
    float* att; cudaGetSymbolAddress((void**)&att, g_att);
    float* ff;  cudaGetSymbolAddress((void**)&ff,  g_ff);
    float* wqkv;cudaGetSymbolAddress((void**)&wqkv,g_wqkv);
    float* glog;cudaGetSymbolAddress((void**)&glog,g_logits);

    const long long NLOG = (long long)ROWS * VOCAB;
    float* logits = ((long long)out_size >= NLOG) ? (float*)d_out : glog;

    // prepack fused qkv weights
    {
        int total = NL_LAYERS * EMB * E3;
        prepack_qkv<<<(total + 255) / 256, 256>>>(wq, wk, wv);
    }

    // embedding
    embed_kernel<<<(ROWS * EMB + 255) / 256, 256>>>(ids, tok_emb, pos_emb);

    for (int l = 0; l < NL_LAYERS; l++) {
        const float* g1 = ln1_g + l * EMB;
        const float* bt1 = ln1_b + l * EMB;
        // h = LN(x)
        ln_kernel<<<ROWS, 256>>>(x, g1, bt1, h);
        // qkv = h @ Wqkv
        run_gemm(h, wqkv + (size_t)l * EMB * E3, nullptr, nullptr, qkv,
                 ROWS, E3, EMB, 0);
        // attention
        attn_kernel<<<BATCH * N_HEADS * SEQ_T, 128>>>(qkv, att);
        // x = x + att @ wo + bo
        run_gemm(att, wo + (size_t)l * EMB * EMB, bo + l * EMB, x, x,
                 ROWS, EMB, EMB, 0);
        // h = LN(x)   (reference reuses ln1 before FFN)
        ln_kernel<<<ROWS, 256>>>(x, g1, bt1, h);
        // ff = relu(h @ w1 + b1)
        run_gemm(h, w1 + (size_t)l * EMB * FF_DIM, b1 + l * FF_DIM, nullptr, ff,
                 ROWS, FF_DIM, EMB, 1);
        // x = x + ff @ w2 + b2
        run_gemm(ff, w2 + (size_t)l * FF_DIM * EMB, b2 + l * EMB, x, x,
                 ROWS, EMB, FF_DIM, 0);
    }

    // final LN + lm head
    ln_kernel<<<ROWS, 256>>>(x, lnf_g, lnf_b, h);
    run_gemm(h, lm_w, lm_b, nullptr, logits, ROWS, VOCAB, EMB, 0);

    // loss (deterministic two-stage reduction)
    if (out_size == 1 || (long long)out_size > NLOG) {
        loss_rows_kernel<<<ROWS, 256>>>(logits, targets);
        float* loss_dst = (out_size == 1) ? (float*)d_out
                                          : ((float*)d_out + NLOG);
        loss_final_kernel<<<1, 256>>>(loss_dst);
    }
}

// round 4
// speedup vs baseline: 6.3138x; 2.6261x over previous
#include <cuda_runtime.h>
#include <cuda_bf16.h>
#include <math.h>
#include <stdint.h>

// ---------------- problem constants ----------------
#define NL_LAYERS 3
#define N_HEADS   16
#define EMB       1024
#define HEAD_DIM  64
#define SEQ_T     1024
#define BATCH     4
#define ROWS      (BATCH * SEQ_T)      // 4096
#define VOCAB     32000
#define E3        (3 * EMB)            // 3072
#define FF_DIM    (4 * EMB)            // 4096
#define LN_EPS    1e-5f
#define ATT_SCALE 0.03125f             // 1/sqrt(EMB) = 1/32

// ---------------- scratch (device globals; no allocation allowed) ----------------
__device__ float g_x   [ROWS * EMB];
__device__ float g_h   [ROWS * EMB];
__device__ float g_qkv [ROWS * E3];
__device__ float g_att [ROWS * EMB];
__device__ float g_ff  [ROWS * FF_DIM];
__device__ float g_wqkv[NL_LAYERS * EMB * E3];       // prepacked + tf32-rounded
__device__ float g_wo  [NL_LAYERS * EMB * EMB];      // tf32-rounded copies
__device__ float g_w1  [NL_LAYERS * EMB * FF_DIM];
__device__ float g_w2  [NL_LAYERS * FF_DIM * EMB];
__device__ float g_lmw [EMB * VOCAB];
__device__ float g_logits[(size_t)ROWS * VOCAB];
__device__ float g_rowloss[ROWS];

// ---------------- tf32 helpers ----------------
__device__ __forceinline__ unsigned int f2tf32(float f) {
    unsigned int u;
    asm("cvt.rna.tf32.f32 %0, %1;" : "=r"(u) : "f"(f));
    return u;
}
__device__ __forceinline__ float tf32r(float f) {   // tf32-rounded fp32 value
    return __uint_as_float(f2tf32(f));
}

#define MMA_TF32(d, a, b)                                                     \
    asm volatile("mma.sync.aligned.m16n8k8.row.col.f32.tf32.tf32.f32 "        \
                 "{%0,%1,%2,%3}, {%4,%5,%6,%7}, {%8,%9}, {%0,%1,%2,%3};"      \
                 : "+f"(d[0]), "+f"(d[1]), "+f"(d[2]), "+f"(d[3])             \
                 : "r"(a[0]), "r"(a[1]), "r"(a[2]), "r"(a[3]),                \
                   "r"(b[0]), "r"(b[1]))

#define CP_ASYNC16(dst, src)                                                  \
    asm volatile("cp.async.cg.shared.global [%0], [%1], 16;" ::               \
                 "r"(dst), "l"(src))
#define CP_COMMIT() asm volatile("cp.async.commit_group;")
#define CP_WAIT(n)  asm volatile("cp.async.wait_group %0;" :: "n"(n))

// ---------------- prepack wq/wk/wv -> [l][e][3E] (tf32-rounded) ----------------
__global__ void prepack_qkv(const float* __restrict__ wq,
                            const float* __restrict__ wk,
                            const float* __restrict__ wv) {
    int idx = blockIdx.x * blockDim.x + threadIdx.x;
    int total = NL_LAYERS * EMB * E3;
    if (idx >= total) return;
    int l = idx / (EMB * E3);
    int r = idx % (EMB * E3);
    int e = r / E3;
    int c = r % E3;
    float v;
    if (c < EMB) {
        int h = c >> 6, d = c & 63;
        v = wq[(((size_t)l * N_HEADS + h) * EMB + e) * HEAD_DIM + d];
    } else if (c < 2 * EMB) {
        int c2 = c - EMB; int h = c2 >> 6, d = c2 & 63;
        v = wk[(((size_t)l * N_HEADS + h) * EMB + e) * HEAD_DIM + d];
    } else {
        int c2 = c - 2 * EMB; int h = c2 >> 6, d = c2 & 63;
        v = wv[(((size_t)l * N_HEADS + h) * EMB + e) * HEAD_DIM + d];
    }
    g_wqkv[idx] = tf32r(v);
}

// ---------------- generic tf32-rounding copy (float4) ----------------
__global__ void cvt_kernel(const float* __restrict__ src, float* __restrict__ dst,
                           int n4) {
    int i = blockIdx.x * blockDim.x + threadIdx.x;
    if (i >= n4) return;
    float4 v = ((const float4*)src)[i];
    v.x = tf32r(v.x); v.y = tf32r(v.y); v.z = tf32r(v.z); v.w = tf32r(v.w);
    ((float4*)dst)[i] = v;
}

// ---------------- embedding ----------------
__global__ void embed_kernel(const int* __restrict__ ids,
                             const float* __restrict__ tok_emb,
                             const float* __restrict__ pos_emb) {
    int idx = blockIdx.x * blockDim.x + threadIdx.x;
    if (idx >= ROWS * EMB) return;
    int row = idx >> 10;
    int e   = idx & 1023;
    int t   = row & (SEQ_T - 1);
    int tok = ids[row];
    g_x[idx] = tok_emb[(size_t)tok * EMB + e] + pos_emb[(size_t)t * EMB + e];
}

// ---------------- layernorm (tf32-rounded output: feeds GEMMs only) ----------------
__global__ void ln_kernel(const float* __restrict__ in,
                          const float* __restrict__ gamma,
                          const float* __restrict__ beta,
                          float* __restrict__ out) {
    int row = blockIdx.x;
    int tid = threadIdx.x;                 // 256 threads
    const float* p = in + (size_t)row * EMB;
    float s = 0.f, s2 = 0.f;
    #pragma unroll
    for (int i = 0; i < 4; i++) {
        float v = p[tid + i * 256];
        s += v; s2 += v * v;
    }
    __shared__ float rs[256], rs2[256];
    rs[tid] = s; rs2[tid] = s2;
    __syncthreads();
    for (int st = 128; st > 0; st >>= 1) {
        if (tid < st) { rs[tid] += rs[tid + st]; rs2[tid] += rs2[tid + st]; }
        __syncthreads();
    }
    float mu  = rs[0]  * (1.0f / EMB);
    float var = rs2[0] * (1.0f / EMB) - mu * mu;
    float inv = rsqrtf(var + LN_EPS);
    float* o = out + (size_t)row * EMB;
    #pragma unroll
    for (int i = 0; i < 4; i++) {
        int e = tid + i * 256;
        o[e] = tf32r((p[e] - mu) * inv * gamma[e] + beta[e]);
    }
}

// ---------------- TF32 tensor-core GEMM v2 (cp.async double-buffered) ----------------
// Inputs A,B are already tf32-rounded fp32. C fp32 (+bias)(+res)(relu)(out_cvt).
#define TBM 128
#define TBN 128
#define TBK 32
#define ASTRIDE 36
#define BSTRIDE 136
#define ASZ (TBM * ASTRIDE)
#define BSZ (TBK * BSTRIDE)
#define GEMM_SMEM ((2 * (ASZ + BSZ)) * 4)

__global__ __launch_bounds__(256, 2)
void tgemm2(const float* __restrict__ A, const float* __restrict__ B,
            const float* __restrict__ bias, const float* __restrict__ res,
            float* __restrict__ C, int M, int N, int K, int relu, int out_cvt) {
    extern __shared__ unsigned int smem[];
    unsigned int* As = smem;                 // 2 stages
    unsigned int* Bs = smem + 2 * ASZ;       // 2 stages

    const int tid  = threadIdx.x;
    const int lane = tid & 31;
    const int wid  = tid >> 5;
    const int wm   = (wid & 1) * 64;
    const int wn   = (wid >> 1) * 32;
    const int g    = lane >> 2;
    const int tg   = lane & 3;

    const int brow = blockIdx.y * TBM;
    const int bcol = blockIdx.x * TBN;

    const float* Ab = A + (size_t)brow * K;
    const float* Bb = B + bcol;

    const int arow = tid >> 3;              // 0..31 (+i*32)
    const int acg  = (tid & 7) * 4;
    const int brw  = tid >> 5;              // 0..7 (+i*8)
    const int bcg  = (tid & 31) * 4;

    const unsigned int sA = (unsigned int)__cvta_generic_to_shared(As);
    const unsigned int sB = (unsigned int)__cvta_generic_to_shared(Bs);

    float acc[4][4][4];
    #pragma unroll
    for (int i = 0; i < 4; i++)
        #pragma unroll
        for (int j = 0; j < 4; j++)
            #pragma unroll
            for (int c = 0; c < 4; c++) acc[i][j][c] = 0.f;

    const int KT = K / TBK;

    // async load of one stage
    #define LOAD_STAGE(stg, kt_)                                              \
    do {                                                                      \
        int k0 = (kt_) * TBK;                                                 \
        _Pragma("unroll")                                                     \
        for (int i = 0; i < 4; i++) {                                         \
            int r = arow + i * 32;                                            \
            CP_ASYNC16(sA + ((stg) * ASZ + r * ASTRIDE + acg) * 4,            \
                       Ab + (size_t)r * K + k0 + acg);                        \
        }                                                                     \
        _Pragma("unroll")                                                     \
        for (int i = 0; i < 4; i++) {                                         \
            int r = brw + i * 8;                                              \
            CP_ASYNC16(sB + ((stg) * BSZ + r * BSTRIDE + bcg) * 4,            \
                       Bb + (size_t)(k0 + r) * N + bcg);                      \
        }                                                                     \
        CP_COMMIT();                                                          \
    } while (0)

    LOAD_STAGE(0, 0);

    for (int kt = 0; kt < KT; kt++) {
        const int cur = kt & 1;
        if (kt + 1 < KT) {
            LOAD_STAGE(cur ^ 1, kt + 1);
            CP_WAIT(1);
        } else {
            CP_WAIT(0);
        }
        __syncthreads();

        const unsigned int* Ac = As + cur * ASZ;
        const unsigned int* Bc = Bs + cur * BSZ;
        #pragma unroll
        for (int ks = 0; ks < 4; ks++) {
            const int k = ks * 8 + tg;
            unsigned int af[4][4], bf[4][2];
            #pragma unroll
            for (int mt = 0; mt < 4; mt++) {
                int r = wm + mt * 16 + g;
                af[mt][0] = Ac[r * ASTRIDE + k];
                af[mt][1] = Ac[(r + 8) * ASTRIDE + k];
                af[mt][2] = Ac[r * ASTRIDE + k + 4];
                af[mt][3] = Ac[(r + 8) * ASTRIDE + k + 4];
            }
            #pragma unroll
            for (int nt = 0; nt < 4; nt++) {
                int c = wn + nt * 8 + g;
                bf[nt][0] = Bc[k * BSTRIDE + c];
                bf[nt][1] = Bc[(k + 4) * BSTRIDE + c];
            }
            #pragma unroll
            for (int mt = 0; mt < 4; mt++)
                #pragma unroll
                for (int nt = 0; nt < 4; nt++)
                    MMA_TF32(acc[mt][nt], af[mt], bf[nt]);
        }
        __syncthreads();
    }

    // epilogue
    #pragma unroll
    for (int mt = 0; mt < 4; mt++) {
        int r0 = brow + wm + mt * 16 + g;
        #pragma unroll
        for (int nt = 0; nt < 4; nt++) {
            int c0 = bcol + wn + nt * 8 + tg * 2;
            float b0 = 0.f, b1 = 0.f;
            if (bias) { b0 = bias[c0]; b1 = bias[c0 + 1]; }
            #pragma unroll
            for (int half = 0; half < 2; half++) {
                int r = r0 + half * 8;
                float v0 = acc[mt][nt][half * 2 + 0] + b0;
                float v1 = acc[mt][nt][half * 2 + 1] + b1;
                if (res) {
                    const float2 rr = *(const float2*)(res + (size_t)r * N + c0);
                    v0 += rr.x; v1 += rr.y;
                }
                if (relu) { v0 = fmaxf(v0, 0.f); v1 = fmaxf(v1, 0.f); }
                if (out_cvt) { v0 = tf32r(v0); v1 = tf32r(v1); }
                float2 o; o.x = v0; o.y = v1;
                *(float2*)(C + (size_t)r * N + c0) = o;
            }
        }
    }
}

// ---------------- flash attention ----------------
// grid (T/64, H, B), 256 threads. fp32 SIMT, online softmax.
// Output att is tf32-rounded (feeds proj GEMM).
#define KPAD 68
#define ATTN_SMEM ((64 * 64 + 3 * 64 * KPAD) * 4)

__global__ __launch_bounds__(256)
void flash_attn(const float* __restrict__ qkv, float* __restrict__ att) {
    extern __shared__ float sm[];
    float* Qs = sm;                       // 64 x 64
    float* Ks = sm + 64 * 64;             // 64 x KPAD
    float* Vs = Ks + 64 * KPAD;           // 64 x KPAD
    float* Ps = Vs + 64 * KPAD;           // 64 x KPAD

    const int qt  = blockIdx.x;
    const int h   = blockIdx.y;
    const int b   = blockIdx.z;
    const int tid = threadIdx.x;
    const int ty  = tid >> 4;             // 0..15 (4 rows each)
    const int tx  = tid & 15;             // cols: tx + 16j

    // load Q tile (64x64)
    #pragma unroll
    for (int i = 0; i < 4; i++) {
        int idx = tid + i * 256;
        int r = idx >> 4, c4 = (idx & 15) * 4;
        *(float4*)(Qs + r * 64 + c4) =
            *(const float4*)(qkv + (size_t)(b * SEQ_T + qt * 64 + r) * E3 +
                             h * HEAD_DIM + c4);
    }

    float m[4], l[4], O[4][4];
    #pragma unroll
    for (int i = 0; i < 4; i++) {
        m[i] = -1e30f; l[i] = 0.f;
        #pragma unroll
        for (int j = 0; j < 4; j++) O[i][j] = 0.f;
    }

    for (int kt = 0; kt <= qt; kt++) {
        // load K,V tiles
        #pragma unroll
        for (int i = 0; i < 4; i++) {
            int idx = tid + i * 256;
            int r = idx >> 4, c4 = (idx & 15) * 4;
            size_t base = (size_t)(b * SEQ_T + kt * 64 + r) * E3 + h * HEAD_DIM + c4;
            *(float4*)(Ks + r * KPAD + c4) = *(const float4*)(qkv + base + EMB);
            *(float4*)(Vs + r * KPAD + c4) = *(const float4*)(qkv + base + 2 * EMB);
        }
        __syncthreads();

        // S = Q K^T (thread: rows ty*4+i, cols tx+16j)
        float s[4][4];
        #pragma unroll
        for (int i = 0; i < 4; i++)
            #pragma unroll
            for (int j = 0; j < 4; j++) s[i][j] = 0.f;
        #pragma unroll
        for (int d4 = 0; d4 < 16; d4++) {
            float4 q[4];
            #pragma unroll
            for (int i = 0; i < 4; i++)
                q[i] = *(const float4*)(Qs + (ty * 4 + i) * 64 + d4 * 4);
            #pragma unroll
            for (int j = 0; j < 4; j++) {
                float4 k = *(const float4*)(Ks + (tx + 16 * j) * KPAD + d4 * 4);
                #pragma unroll
                for (int i = 0; i < 4; i++)
                    s[i][j] += q[i].x * k.x + q[i].y * k.y + q[i].z * k.z + q[i].w * k.w;
            }
        }

        // online softmax per row
        #pragma unroll
        for (int i = 0; i < 4; i++) {
            int grow = qt * 64 + ty * 4 + i;
            float mloc = -1e30f;
            #pragma unroll
            for (int j = 0; j < 4; j++) {
                int gcol = kt * 64 + tx + 16 * j;
                float sv = s[i][j] * ATT_SCALE;
                if (gcol > grow) sv = -1e30f;
                s[i][j] = sv;
                mloc = fmaxf(mloc, sv);
            }
            #pragma unroll
            for (int off = 8; off > 0; off >>= 1)
                mloc = fmaxf(mloc, __shfl_xor_sync(0xffffffffu, mloc, off, 16));
            float mnew = fmaxf(m[i], mloc);
            float corr = __expf(m[i] - mnew);
            float rs = 0.f;
            #pragma unroll
            for (int j = 0; j < 4; j++) {
                float p = __expf(s[i][j] - mnew);
                s[i][j] = p; rs += p;
            }
            #pragma unroll
            for (int off = 8; off > 0; off >>= 1)
                rs += __shfl_xor_sync(0xffffffffu, rs, off, 16);
            l[i] = l[i] * corr + rs;
            m[i] = mnew;
            #pragma unroll
            for (int j = 0; j < 4; j++) {
                O[i][j] *= corr;
                Ps[(ty * 4 + i) * KPAD + tx + 16 * j] = s[i][j];
            }
        }
        __syncthreads();

        // O += P V
        #pragma unroll 4
        for (int c = 0; c < 64; c++) {
            float p[4], v[4];
            #pragma unroll
            for (int i = 0; i < 4; i++) p[i] = Ps[(ty * 4 + i) * KPAD + c];
            #pragma unroll
            for (int j = 0; j < 4; j++) v[j] = Vs[c * KPAD + tx + 16 * j];
            #pragma unroll
            for (int i = 0; i < 4; i++)
                #pragma unroll
                for (int j = 0; j < 4; j++)
                    O[i][j] += p[i] * v[j];
        }
        __syncthreads();
    }

    // write out (tf32-rounded: feeds proj GEMM)
    #pragma unroll
    for (int i = 0; i < 4; i++) {
        float inv = 1.0f / l[i];
        size_t rbase = (size_t)(b * SEQ_T + qt * 64 + ty * 4 + i) * EMB + h * HEAD_DIM;
        #pragma unroll
        for (int j = 0; j < 4; j++)
            att[rbase + tx + 16 * j] = tf32r(O[i][j] * inv);
    }
}

// ---------------- loss ----------------
__global__ __launch_bounds__(256)
void loss_rows_kernel(const float* __restrict__ logits, const int* __restrict__ tgt) {
    int row = blockIdx.x;
    int tid = threadIdx.x;
    const float* lp = logits + (size_t)row * VOCAB;
    __shared__ float red[256];
    float m = -1e30f;
    for (int i = tid; i < VOCAB; i += 256) m = fmaxf(m, lp[i]);
    red[tid] = m; __syncthreads();
    for (int st = 128; st > 0; st >>= 1) {
        if (tid < st) red[tid] = fmaxf(red[tid], red[tid + st]);
        __syncthreads();
    }
    m = red[0]; __syncthreads();
    float s = 0.f;
    for (int i = tid; i < VOCAB; i += 256) s += __expf(lp[i] - m);
    red[tid] = s; __syncthreads();
    for (int st = 128; st > 0; st >>= 1) {
        if (tid < st) red[tid] += red[tid + st];
        __syncthreads();
    }
    if (tid == 0)
        g_rowloss[row] = -(lp[tgt[row]] - m - logf(red[0]));
}

__global__ __launch_bounds__(256)
void loss_final_kernel(float* __restrict__ out_loss) {
    int tid = threadIdx.x;
    __shared__ float red[256];
    float s = 0.f;
    #pragma unroll
    for (int i = 0; i < ROWS / 256; i++) s += g_rowloss[tid + i * 256];
    red[tid] = s; __syncthreads();
    for (int st = 128; st > 0; st >>= 1) {
        if (tid < st) red[tid] += red[tid + st];
        __syncthreads();
    }
    if (tid == 0) out_loss[0] = red[0] * (1.0f / ROWS);
}

// ---------------- launch ----------------
static void run_gemm(const float* A, const float* B, const float* bias,
                     const float* res, float* C, int M, int N, int K,
                     int relu, int out_cvt) {
    dim3 grid(N / TBN, M / TBM);
    tgemm2<<<grid, 256, GEMM_SMEM>>>(A, B, bias, res, C, M, N, K, relu, out_cvt);
}

extern "C" void kernel_launch(void* const* d_in, const int* in_sizes, int n_in,
                              void* d_out, int out_size) {
    const int*   ids     = (const int*)  d_in[0];
    const int*   targets = (const int*)  d_in[1];
    const float* tok_emb = (const float*)d_in[2];
    const float* pos_emb = (const float*)d_in[3];
    const float* wq      = (const float*)d_in[4];
    const float* wk      = (const float*)d_in[5];
    const float* wv      = (const float*)d_in[6];
    const float* wo      = (const float*)d_in[7];
    const float* bo      = (const float*)d_in[8];
    const float* ln1_g   = (const float*)d_in[9];
    const float* ln1_b   = (const float*)d_in[10];
    const float* w1      = (const float*)d_in[11];
    const float* b1      = (const float*)d_in[12];
    const float* w2      = (const float*)d_in[13];
    const float* b2      = (const float*)d_in[14];
    const float* lnf_g   = (const float*)d_in[15];
    const float* lnf_b   = (const float*)d_in[16];
    const float* lm_w    = (const float*)d_in[17];
    const float* lm_b    = (const float*)d_in[18];

    static int attr_set = 0;
    if (!attr_set) {
        cudaFuncSetAttribute(tgemm2, cudaFuncAttributeMaxDynamicSharedMemorySize,
                             GEMM_SMEM);
        cudaFuncSetAttribute(flash_attn, cudaFuncAttributeMaxDynamicSharedMemorySize,
                             ATTN_SMEM);
        attr_set = 1;
    }

    float* x;   cudaGetSymbolAddress((void**)&x,   g_x);
    float* h;   cudaGetSymbolAddress((void**)&h,   g_h);
    float* qkv; cudaGetSymbolAddress((void**)&qkv, g_qkv);
    float* att; cudaGetSymbolAddress((void**)&att, g_att);
    float* ff;  cudaGetSymbolAddress((void**)&ff,  g_ff);
    float* wqkvp; cudaGetSymbolAddress((void**)&wqkvp, g_wqkv);
    float* wop;   cudaGetSymbolAddress((void**)&wop,   g_wo);
    float* w1p;   cudaGetSymbolAddress((void**)&w1p,   g_w1);
    float* w2p;   cudaGetSymbolAddress((void**)&w2p,   g_w2);
    float* lmwp;  cudaGetSymbolAddress((void**)&lmwp,  g_lmw);
    float* glog;  cudaGetSymbolAddress((void**)&glog,  g_logits);

    const long long NLOG = (long long)ROWS * VOCAB;
    float* logits = ((long long)out_size >= NLOG) ? (float*)d_out : glog;

    // weight prep (tf32 rounding done once here per launch)
    {
        int total = NL_LAYERS * EMB * E3;
        prepack_qkv<<<(total + 255) / 256, 256>>>(wq, wk, wv);
        int n4;
        n4 = NL_LAYERS * EMB * EMB / 4;
        cvt_kernel<<<(n4 + 255) / 256, 256>>>(wo, wop, n4);
        n4 = NL_LAYERS * EMB * FF_DIM / 4;
        cvt_kernel<<<(n4 + 255) / 256, 256>>>(w1, w1p, n4);
        cvt_kernel<<<(n4 + 255) / 256, 256>>>(w2, w2p, n4);
        n4 = EMB * VOCAB / 4;
        cvt_kernel<<<(n4 + 255) / 256, 256>>>(lm_w, lmwp, n4);
    }

    // embedding
    embed_kernel<<<(ROWS * EMB + 255) / 256, 256>>>(ids, tok_emb, pos_emb);

    dim3 agrid(SEQ_T / 64, N_HEADS, BATCH);
    for (int l = 0; l < NL_LAYERS; l++) {
        const float* g1  = ln1_g + l * EMB;
        const float* bt1 = ln1_b + l * EMB;
        // h = tf32(LN(x))
        ln_kernel<<<ROWS, 256>>>(x, g1, bt1, h);
        // qkv = h @ Wqkv  (fp32 out, feeds attention)
        run_gemm(h, wqkvp + (size_t)l * EMB * E3, nullptr, nullptr, qkv,
                 ROWS, E3, EMB, 0, 0);
        // flash attention -> att (tf32-rounded out)
        flash_attn<<<agrid, 256, ATTN_SMEM>>>(qkv, att);
        // x = x + att @ wo + bo
        run_gemm(att, wop + (size_t)l * EMB * EMB, bo + l * EMB, x, x,
                 ROWS, EMB, EMB, 0, 0);
        // h = tf32(LN(x))
        ln_kernel<<<ROWS, 256>>>(x, g1, bt1, h);
        // ff = tf32(relu(h @ w1 + b1))
        run_gemm(h, w1p + (size_t)l * EMB * FF_DIM, b1 + l * FF_DIM, nullptr, ff,
                 ROWS, FF_DIM, EMB, 1, 1);
        // x = x + ff @ w2 + b2
        run_gemm(ff, w2p + (size_t)l * FF_DIM * EMB, b2 + l * EMB, x, x,
                 ROWS, EMB, FF_DIM, 0, 0);
    }

    // final LN + lm head
    ln_kernel<<<ROWS, 256>>>(x, lnf_g, lnf_b, h);
    run_gemm(h, lmwp, lm_b, nullptr, logits, ROWS, VOCAB, EMB, 0, 0);

    // loss
    if (out_size == 1 || (long long)out_size > NLOG) {
        loss_rows_kernel<<<ROWS, 256>>>(logits, targets);
        float* loss_dst = (out_size == 1) ? (float*)d_out
                                          : ((float*)d_out + NLOG);
        loss_final_kernel<<<1, 256>>>(loss_dst);
    }
}